// round 4
// baseline (speedup 1.0000x reference)
#include <cuda_runtime.h>
#include <cuda_bf16.h>
#include <cstdint>

#define BB 8
#define SS 50
#define II 20
#define CC 64
#define NN 4096
#define MAXM 1024

// ---------------- scratch (device globals; no allocs allowed) ----------------
__device__ float g_sums[BB * NN * CC];           // 8 MB segment sums
__device__ int   g_counts[BB * NN];
__device__ int   g_M[BB];
__device__ float g_accL[BB * NN];
__device__ float g_accN[BB * NN];
// pre-swizzled bf16 operand arrays (SW128-style XOR within 128B rows)
__device__ __nv_bfloat16 g_ehi[NN * CC], g_elo[NN * CC];   // emb hi/lo
__device__ __nv_bfloat16 g_ghi[NN * CC], g_glo[NN * CC];   // (emb@W) hi/lo
__device__ __nv_bfloat16 g_chi[BB * MAXM * CC], g_clo[BB * MAXM * CC]; // cmean hi/lo

// swizzled element index for row r, channel c (64 bf16 = 128B rows)
__device__ __forceinline__ int swz(int r, int c) { return r * CC + (c ^ ((r & 7) << 3)); }

__device__ __forceinline__ uint32_t smem_u32(const void* p) {
    uint32_t a;
    asm("{ .reg .u64 t; cvta.to.shared.u64 t, %1; cvt.u32.u64 %0, t; }" : "=r"(a) : "l"(p));
    return a;
}
__device__ __forceinline__ void ldm4(uint32_t* r, uint32_t addr) {
    asm volatile("ldmatrix.sync.aligned.m8n8.x4.shared.b16 {%0,%1,%2,%3}, [%4];"
        : "=r"(r[0]), "=r"(r[1]), "=r"(r[2]), "=r"(r[3]) : "r"(addr));
}
__device__ __forceinline__ void mma16816(float* c, const uint32_t* a, uint32_t b0, uint32_t b1) {
    asm volatile("mma.sync.aligned.m16n8k16.row.col.f32.bf16.bf16.f32 "
        "{%0,%1,%2,%3}, {%4,%5,%6,%7}, {%8,%9}, {%0,%1,%2,%3};"
        : "+f"(c[0]), "+f"(c[1]), "+f"(c[2]), "+f"(c[3])
        : "r"(a[0]), "r"(a[1]), "r"(a[2]), "r"(a[3]), "r"(b0), "r"(b1));
}

// ---------------- K0: zero scratch + gmat + bf16 split conversion ----------------
__global__ void k_prep(const float* __restrict__ emb, const float* __restrict__ W) {
    int t = threadIdx.x;
    if (blockIdx.x < 256) {
        __shared__ float Ws[CC * CC];
        __shared__ float Es[16 * CC];
        for (int k = t; k < CC * CC; k += 256) Ws[k] = W[k];
        int nbase = blockIdx.x * 16;
        for (int k = t; k < 16 * CC; k += 256) Es[k] = emb[(size_t)nbase * CC + k];
        __syncthreads();
        int c = t & (CC - 1);
        int rg = t >> 6;
#pragma unroll
        for (int it = 0; it < 4; it++) {
            int r = it * 4 + rg;
            float a0 = 0.0f, a1 = 0.0f;
#pragma unroll
            for (int cp = 0; cp < CC; cp += 2) {
                a0 = fmaf(Es[r * CC + cp],     Ws[cp * CC + c],       a0);
                a1 = fmaf(Es[r * CC + cp + 1], Ws[(cp + 1) * CC + c], a1);
            }
            float gv = a0 + a1;
            float ev = Es[r * CC + c];
            int si = swz(nbase + r, c);
            __nv_bfloat16 eh = __float2bfloat16(ev);
            __nv_bfloat16 el = __float2bfloat16(ev - __bfloat162float(eh));
            __nv_bfloat16 gh = __float2bfloat16(gv);
            __nv_bfloat16 gl = __float2bfloat16(gv - __bfloat162float(gh));
            g_ehi[si] = eh; g_elo[si] = el;
            g_ghi[si] = gh; g_glo[si] = gl;
        }
    } else {
        int i = (blockIdx.x - 256) * 256 + t;
        for (int k = i; k < BB * NN * CC; k += 2048 * 256) g_sums[k] = 0.0f;
        if (i < BB * NN) { g_counts[i] = 0; g_accL[i] = 0.0f; g_accN[i] = 0.0f; }
    }
}

// ---------------- K1: masked scatter-add ----------------
__global__ void k_scatter(const float* __restrict__ x, const int* __restrict__ ids,
                          const int* __restrict__ slen) {
    int t = blockIdx.x * blockDim.x + threadIdx.x;
    if (t >= BB * SS * II * CC) return;
    int c = t & (CC - 1);
    int e = t >> 6;
    int bs = e / II;
    int s = bs % SS;
    int b = bs / SS;
    if (s < slen[b]) {
        int id = ids[e];
        atomicAdd(&g_sums[(((size_t)b * NN + id) << 6) + c], x[t]);
        if (c == 0) atomicAdd(&g_counts[b * NN + id], 1);
    }
}

// ---------------- K2: compaction + mean + bf16 split (swizzled) ----------------
__global__ void k_compact() {
    __shared__ int wsum[32];
    int b = blockIdx.x;
    int t = threadIdx.x;          // 1024 threads, 4 ids each
    int base = b * NN;
    int cnts[4], flags[4];
    int local = 0;
#pragma unroll
    for (int j = 0; j < 4; j++) {
        int cnt = g_counts[base + t * 4 + j];
        cnts[j] = cnt; flags[j] = (cnt > 0); local += flags[j];
    }
    int lane = t & 31, wid = t >> 5;
    int v = local;
#pragma unroll
    for (int off = 1; off < 32; off <<= 1) {
        int u = __shfl_up_sync(0xffffffffu, v, off);
        if (lane >= off) v += u;
    }
    if (lane == 31) wsum[wid] = v;
    __syncthreads();
    if (wid == 0) {
        int w = wsum[lane];
#pragma unroll
        for (int off = 1; off < 32; off <<= 1) {
            int u = __shfl_up_sync(0xffffffffu, w, off);
            if (lane >= off) w += u;
        }
        wsum[lane] = w;
    }
    __syncthreads();
    int warpBase = (wid == 0) ? 0 : wsum[wid - 1];
    int excl = warpBase + v - local;
#pragma unroll
    for (int j = 0; j < 4; j++) {
        if (flags[j]) {
            int slot = excl++;
            float inv = 1.0f / (float)cnts[j];
            const float4* src = reinterpret_cast<const float4*>(&g_sums[((size_t)(base + t * 4 + j)) << 6]);
            int row = b * MAXM + slot;
#pragma unroll
            for (int k = 0; k < 16; k++) {
                float4 q = src[k];
                float vs[4] = {q.x * inv, q.y * inv, q.z * inv, q.w * inv};
#pragma unroll
                for (int u2 = 0; u2 < 4; u2++) {
                    int si = swz(row, k * 4 + u2);
                    __nv_bfloat16 h = __float2bfloat16(vs[u2]);
                    g_chi[si] = h;
                    g_clo[si] = __float2bfloat16(vs[u2] - __bfloat162float(h));
                }
            }
        }
    }
    if (t == 0) g_M[b] = wsum[31];
}

// ---------------- K3: warp-MMA tile kernel (HMMA via mma.sync) ----------------
// bid = mt*512 + b*64 + nt. Per CTA: 64n x 64m tile of S and T for batch b.
// 8 warps = 4(n) x 2(m); warp = 16n x 32m per output.
#define SM_EHI 0
#define SM_ELO 8192
#define SM_GHI 16384
#define SM_GLO 24576
#define SM_CHI 32768
#define SM_CLO 40960

__global__ void __launch_bounds__(256) k_mma() {
    __shared__ __align__(1024) char smem[49152];
    int t = threadIdx.x;
    int bid = blockIdx.x;
    int nt = bid & 63;
    int b  = (bid >> 6) & 7;
    int mt = bid >> 9;
    int M = g_M[b];
    int m0 = mt * 64;
    if (m0 >= M) return;
    int mEnd = min(64, M - m0);

    // ---- stage tiles (arrays pre-swizzled -> straight copies) ----
    {
        int arow = nt * 512;                       // uint4 offset: 64 rows * 8
        const uint4* s_eh = reinterpret_cast<const uint4*>(g_ehi) + arow;
        const uint4* s_el = reinterpret_cast<const uint4*>(g_elo) + arow;
        const uint4* s_gh = reinterpret_cast<const uint4*>(g_ghi) + arow;
        const uint4* s_gl = reinterpret_cast<const uint4*>(g_glo) + arow;
        uint4* d_eh = reinterpret_cast<uint4*>(smem + SM_EHI);
        uint4* d_el = reinterpret_cast<uint4*>(smem + SM_ELO);
        uint4* d_gh = reinterpret_cast<uint4*>(smem + SM_GHI);
        uint4* d_gl = reinterpret_cast<uint4*>(smem + SM_GLO);
        for (int k = t; k < 512; k += 256) {
            d_eh[k] = s_eh[k]; d_el[k] = s_el[k];
            d_gh[k] = s_gh[k]; d_gl[k] = s_gl[k];
        }
        int brow = (b * MAXM + m0) * 8;
        const uint4* s_ch = reinterpret_cast<const uint4*>(g_chi) + brow;
        const uint4* s_cl = reinterpret_cast<const uint4*>(g_clo) + brow;
        uint4* d_ch = reinterpret_cast<uint4*>(smem + SM_CHI);
        uint4* d_cl = reinterpret_cast<uint4*>(smem + SM_CLO);
        int cnt = mEnd * 8;
        for (int k = t; k < cnt; k += 256) { d_ch[k] = s_ch[k]; d_cl[k] = s_cl[k]; }
    }
    __syncthreads();

    int lane = t & 31, wid = t >> 5;
    int wn = wid & 3, wm = wid >> 2;
    int mat = lane >> 3, rw = lane & 7;
    uint32_t sb = smem_u32(smem);

    // A fragment lane address skeleton (row term + swizzle seed; XOR colgrp<<4)
    int rowA = wn * 16 + ((mat & 1) << 3) + rw;
    uint32_t xA = (uint32_t)(rowA * 128 + ((rowA & 7) << 4));
    int cgA = mat >> 1;
    // B fragment lane address skeleton (two 16-row groups)
    int rowB = wm * 32 + ((mat >> 1) << 3) + rw;
    uint32_t xB0 = (uint32_t)(rowB * 128 + ((rowB & 7) << 4));
    uint32_t xB1 = xB0 + 16 * 128;
    int cgB = mat & 1;

    float aS[4][4], aT[4][4];
#pragma unroll
    for (int f = 0; f < 4; f++)
#pragma unroll
        for (int j = 0; j < 4; j++) { aS[f][j] = 0.0f; aT[f][j] = 0.0f; }

    const uint32_t aeOff[3] = {SM_EHI, SM_EHI, SM_ELO};
    const uint32_t agOff[3] = {SM_GHI, SM_GHI, SM_GLO};
    const uint32_t bOff[3]  = {SM_CHI, SM_CLO, SM_CHI};

#pragma unroll
    for (int p = 0; p < 3; p++) {
#pragma unroll
        for (int k16 = 0; k16 < 4; k16++) {
            uint32_t ae[4], ag[4];
            uint32_t cA = (uint32_t)((2 * k16 + cgA) << 4);
            ldm4(ae, sb + aeOff[p] + (xA ^ cA));
            ldm4(ag, sb + agOff[p] + (xA ^ cA));
            uint32_t cB = (uint32_t)((2 * k16 + cgB) << 4);
#pragma unroll
            for (int g2 = 0; g2 < 2; g2++) {
                uint32_t bb[4];
                ldm4(bb, sb + bOff[p] + ((g2 ? xB1 : xB0) ^ cB));
                mma16816(aS[2 * g2],     ae, bb[0], bb[1]);
                mma16816(aS[2 * g2 + 1], ae, bb[2], bb[3]);
                mma16816(aT[2 * g2],     ag, bb[0], bb[1]);
                mma16816(aT[2 * g2 + 1], ag, bb[2], bb[3]);
            }
        }
    }

    // ---- fused epilogue: leaky + exp, reduce over m, atomic partials ----
    float l1 = 0.0f, v1 = 0.0f, l2 = 0.0f, v2 = 0.0f;
#pragma unroll
    for (int f = 0; f < 4; f++) {
        int mloc = wm * 32 + f * 8 + ((lane & 3) << 1);
#pragma unroll
        for (int j = 0; j < 2; j++) {
            if (mloc + j < mEnd) {
                float s = aS[f][j];
                s = fmaxf(s, 0.0f) + 0.2f * fminf(s, 0.0f);
                float e = __expf(s);
                l1 += e; v1 = fmaf(e, aT[f][j], v1);
                float s2 = aS[f][j + 2];
                s2 = fmaxf(s2, 0.0f) + 0.2f * fminf(s2, 0.0f);
                float e2 = __expf(s2);
                l2 += e2; v2 = fmaf(e2, aT[f][j + 2], v2);
            }
        }
    }
#pragma unroll
    for (int off = 1; off < 4; off <<= 1) {
        l1 += __shfl_xor_sync(0xffffffffu, l1, off);
        v1 += __shfl_xor_sync(0xffffffffu, v1, off);
        l2 += __shfl_xor_sync(0xffffffffu, l2, off);
        v2 += __shfl_xor_sync(0xffffffffu, v2, off);
    }
    if ((lane & 3) == 0) {
        int n1 = nt * 64 + wn * 16 + (lane >> 2);
        int idx = b * NN + n1;
        atomicAdd(&g_accL[idx], l1);
        atomicAdd(&g_accN[idx], v1);
        atomicAdd(&g_accL[idx + 8], l2);
        atomicAdd(&g_accN[idx + 8], v2);
    }
}

// ---------------- K4: finalize ----------------
__global__ void k_final(const float* __restrict__ emb, const float* __restrict__ pb,
                        float* __restrict__ out) {
    __shared__ float pbs[CC];
    int t = threadIdx.x;
    if (t < CC) pbs[t] = pb[t];
    __syncthreads();
    int i = blockIdx.x * 256 + t;
    int n = i & (NN - 1);
    const float* er = emb + (size_t)n * CC;
    float h = 0.0f;
#pragma unroll
    for (int c = 0; c < CC; c++) h = fmaf(er[c], pbs[c], h);
    float l = g_accL[i];
    out[i] = (l > 0.0f) ? (g_accN[i] / l + h) : h;
}

extern "C" void kernel_launch(void* const* d_in, const int* in_sizes, int n_in,
                              void* d_out, int out_size) {
    const float* x    = (const float*)d_in[0];
    const float* emb  = (const float*)d_in[1];
    const float* W    = (const float*)d_in[2];
    const float* pb   = (const float*)d_in[3];
    const int*   ids  = (const int*)d_in[4];
    const int*   slen = (const int*)d_in[5];
    float* out = (float*)d_out;

    k_prep<<<2304, 256>>>(emb, W);
    k_scatter<<<(BB * SS * II * CC + 255) / 256, 256>>>(x, ids, slen);
    k_compact<<<BB, 1024>>>();
    k_mma<<<16 * BB * 64, 256>>>();
    k_final<<<(BB * NN) / 256, 256>>>(emb, pb, out);
}

// round 6
// speedup vs baseline: 1.8518x; 1.8518x over previous
#include <cuda_runtime.h>
#include <cuda_bf16.h>
#include <cstdint>

#define BB 8
#define SS 50
#define II 20
#define CC 64
#define NN 4096
#define MAXM 1024

// ---------------- scratch (device globals; no allocs allowed) ----------------
__device__ float g_sums[BB * NN * CC];           // 8 MB segment sums
__device__ int   g_counts[BB * NN];
__device__ int   g_M[BB];
__device__ float g_accL[BB * NN];
__device__ float g_accN[BB * NN];
__device__ float g_cmean[BB * MAXM * CC];        // compacted means (fp32)
// pre-swizzled bf16 operand arrays (SW128-style XOR within 128B rows)
__device__ __nv_bfloat16 g_ehi[NN * CC], g_elo[NN * CC];   // emb hi/lo
__device__ __nv_bfloat16 g_ghi[NN * CC], g_glo[NN * CC];   // (emb@W) hi/lo
__device__ __nv_bfloat16 g_chi[BB * MAXM * CC], g_clo[BB * MAXM * CC]; // cmean hi/lo

// swizzled element index for row r, channel c (64 bf16 = 128B rows)
__device__ __forceinline__ int swz(int r, int c) { return r * CC + (c ^ ((r & 7) << 3)); }

__device__ __forceinline__ uint32_t smem_u32(const void* p) {
    uint32_t a;
    asm("{ .reg .u64 t; cvta.to.shared.u64 t, %1; cvt.u32.u64 %0, t; }" : "=r"(a) : "l"(p));
    return a;
}
__device__ __forceinline__ void ldm4(uint32_t* r, uint32_t addr) {
    asm volatile("ldmatrix.sync.aligned.m8n8.x4.shared.b16 {%0,%1,%2,%3}, [%4];"
        : "=r"(r[0]), "=r"(r[1]), "=r"(r[2]), "=r"(r[3]) : "r"(addr));
}
__device__ __forceinline__ void mma16816(float* c, const uint32_t* a, uint32_t b0, uint32_t b1) {
    asm volatile("mma.sync.aligned.m16n8k16.row.col.f32.bf16.bf16.f32 "
        "{%0,%1,%2,%3}, {%4,%5,%6,%7}, {%8,%9}, {%0,%1,%2,%3};"
        : "+f"(c[0]), "+f"(c[1]), "+f"(c[2]), "+f"(c[3])
        : "r"(a[0]), "r"(a[1]), "r"(a[2]), "r"(a[3]), "r"(b0), "r"(b1));
}

// ---------------- K0: zero scratch + gmat + e/g bf16 split ----------------
__global__ void k_prep(const float* __restrict__ emb, const float* __restrict__ W) {
    int t = threadIdx.x;
    if (blockIdx.x < 256) {
        __shared__ float Ws[CC * CC];
        __shared__ float Es[16 * CC];
        for (int k = t; k < CC * CC; k += 256) Ws[k] = W[k];
        int nbase = blockIdx.x * 16;
        for (int k = t; k < 16 * CC; k += 256) Es[k] = emb[(size_t)nbase * CC + k];
        __syncthreads();
        int c = t & (CC - 1);
        int rg = t >> 6;
#pragma unroll
        for (int it = 0; it < 4; it++) {
            int r = it * 4 + rg;
            float a0 = 0.0f, a1 = 0.0f;
#pragma unroll
            for (int cp = 0; cp < CC; cp += 2) {
                a0 = fmaf(Es[r * CC + cp],     Ws[cp * CC + c],       a0);
                a1 = fmaf(Es[r * CC + cp + 1], Ws[(cp + 1) * CC + c], a1);
            }
            float gv = a0 + a1;
            float ev = Es[r * CC + c];
            int si = swz(nbase + r, c);
            __nv_bfloat16 eh = __float2bfloat16(ev);
            __nv_bfloat16 el = __float2bfloat16(ev - __bfloat162float(eh));
            __nv_bfloat16 gh = __float2bfloat16(gv);
            __nv_bfloat16 gl = __float2bfloat16(gv - __bfloat162float(gh));
            g_ehi[si] = eh; g_elo[si] = el;
            g_ghi[si] = gh; g_glo[si] = gl;
        }
    } else {
        int i = (blockIdx.x - 256) * 256 + t;
        for (int k = i; k < BB * NN * CC; k += 2048 * 256) g_sums[k] = 0.0f;
        if (i < BB * NN) { g_counts[i] = 0; g_accL[i] = 0.0f; g_accN[i] = 0.0f; }
    }
}

// ---------------- K1: masked scatter-add ----------------
__global__ void k_scatter(const float* __restrict__ x, const int* __restrict__ ids,
                          const int* __restrict__ slen) {
    int t = blockIdx.x * blockDim.x + threadIdx.x;
    if (t >= BB * SS * II * CC) return;
    int c = t & (CC - 1);
    int e = t >> 6;
    int bs = e / II;
    int s = bs % SS;
    int b = bs / SS;
    if (s < slen[b]) {
        int id = ids[e];
        atomicAdd(&g_sums[(((size_t)b * NN + id) << 6) + c], x[t]);
        if (c == 0) atomicAdd(&g_counts[b * NN + id], 1);
    }
}

// ---------------- K2: compaction + mean (fp32, coalesced float4) ----------------
__global__ void k_compact() {
    __shared__ int wsum[32];
    int b = blockIdx.x;
    int t = threadIdx.x;          // 1024 threads, 4 ids each
    int base = b * NN;
    int cnts[4], flags[4];
    int local = 0;
#pragma unroll
    for (int j = 0; j < 4; j++) {
        int cnt = g_counts[base + t * 4 + j];
        cnts[j] = cnt; flags[j] = (cnt > 0); local += flags[j];
    }
    int lane = t & 31, wid = t >> 5;
    int v = local;
#pragma unroll
    for (int off = 1; off < 32; off <<= 1) {
        int u = __shfl_up_sync(0xffffffffu, v, off);
        if (lane >= off) v += u;
    }
    if (lane == 31) wsum[wid] = v;
    __syncthreads();
    if (wid == 0) {
        int w = wsum[lane];
#pragma unroll
        for (int off = 1; off < 32; off <<= 1) {
            int u = __shfl_up_sync(0xffffffffu, w, off);
            if (lane >= off) w += u;
        }
        wsum[lane] = w;
    }
    __syncthreads();
    int warpBase = (wid == 0) ? 0 : wsum[wid - 1];
    int excl = warpBase + v - local;
#pragma unroll
    for (int j = 0; j < 4; j++) {
        if (flags[j]) {
            int slot = excl++;
            float inv = 1.0f / (float)cnts[j];
            const float4* src = reinterpret_cast<const float4*>(&g_sums[((size_t)(base + t * 4 + j)) << 6]);
            float4* dst = reinterpret_cast<float4*>(&g_cmean[((size_t)(b * MAXM + slot)) << 6]);
#pragma unroll
            for (int k = 0; k < 16; k++) {
                float4 q = src[k];
                q.x *= inv; q.y *= inv; q.z *= inv; q.w *= inv;
                dst[k] = q;
            }
        }
    }
    if (t == 0) g_M[b] = wsum[31];
}

// ---------------- K2b: warp-per-row bf16 split of cmean (coalesced) ----------------
__global__ void k_cvt() {
    int t = threadIdx.x;
    int lane = t & 31;
    int row = blockIdx.x * 8 + (t >> 5);     // 8192 rows total
    int c0 = lane * 2;
    const float2* src = reinterpret_cast<const float2*>(g_cmean + (size_t)row * CC) + lane;
    float2 v = *src;
    __nv_bfloat16 h0 = __float2bfloat16(v.x);
    __nv_bfloat16 l0 = __float2bfloat16(v.x - __bfloat162float(h0));
    __nv_bfloat16 h1 = __float2bfloat16(v.y);
    __nv_bfloat16 l1 = __float2bfloat16(v.y - __bfloat162float(h1));
    uint32_t hp = (uint32_t)__bfloat16_as_ushort(h0) | ((uint32_t)__bfloat16_as_ushort(h1) << 16);
    uint32_t lp = (uint32_t)__bfloat16_as_ushort(l0) | ((uint32_t)__bfloat16_as_ushort(l1) << 16);
    int cs = c0 ^ ((row & 7) << 3);          // XOR hits bits 3-5 only: pair stays intact
    int ui = row * 32 + (cs >> 1);
    reinterpret_cast<uint32_t*>(g_chi)[ui] = hp;
    reinterpret_cast<uint32_t*>(g_clo)[ui] = lp;
}

// ---------------- K3: warp-MMA tile kernel (HMMA via mma.sync) ----------------
// bid = mt*512 + b*64 + nt. Per CTA: 64n x 64m tile of S and T for batch b.
#define SM_EHI 0
#define SM_ELO 8192
#define SM_GHI 16384
#define SM_GLO 24576
#define SM_CHI 32768
#define SM_CLO 40960

__global__ void __launch_bounds__(256, 2) k_mma() {
    __shared__ __align__(1024) char smem[49152];
    int t = threadIdx.x;
    int bid = blockIdx.x;
    int nt = bid & 63;
    int b  = (bid >> 6) & 7;
    int mt = bid >> 9;
    int M = g_M[b];
    int m0 = mt * 64;
    if (m0 >= M) return;
    int mEnd = min(64, M - m0);

    // ---- stage tiles (arrays pre-swizzled -> straight copies) ----
    {
        int arow = nt * 512;                       // uint4 offset: 64 rows * 8
        const uint4* s_eh = reinterpret_cast<const uint4*>(g_ehi) + arow;
        const uint4* s_el = reinterpret_cast<const uint4*>(g_elo) + arow;
        const uint4* s_gh = reinterpret_cast<const uint4*>(g_ghi) + arow;
        const uint4* s_gl = reinterpret_cast<const uint4*>(g_glo) + arow;
        uint4* d_eh = reinterpret_cast<uint4*>(smem + SM_EHI);
        uint4* d_el = reinterpret_cast<uint4*>(smem + SM_ELO);
        uint4* d_gh = reinterpret_cast<uint4*>(smem + SM_GHI);
        uint4* d_gl = reinterpret_cast<uint4*>(smem + SM_GLO);
        for (int k = t; k < 512; k += 256) {
            d_eh[k] = s_eh[k]; d_el[k] = s_el[k];
            d_gh[k] = s_gh[k]; d_gl[k] = s_gl[k];
        }
        int brow = (b * MAXM + m0) * 8;
        const uint4* s_ch = reinterpret_cast<const uint4*>(g_chi) + brow;
        const uint4* s_cl = reinterpret_cast<const uint4*>(g_clo) + brow;
        uint4* d_ch = reinterpret_cast<uint4*>(smem + SM_CHI);
        uint4* d_cl = reinterpret_cast<uint4*>(smem + SM_CLO);
        int cnt = mEnd * 8;
        for (int k = t; k < cnt; k += 256) { d_ch[k] = s_ch[k]; d_cl[k] = s_cl[k]; }
    }
    __syncthreads();

    int lane = t & 31, wid = t >> 5;
    int wn = wid & 3, wm = wid >> 2;
    int mat = lane >> 3, rw = lane & 7;
    uint32_t sb = smem_u32(smem);

    int rowA = wn * 16 + ((mat & 1) << 3) + rw;
    uint32_t xA = (uint32_t)(rowA * 128 + ((rowA & 7) << 4));
    int cgA = mat >> 1;
    int rowB = wm * 32 + ((mat >> 1) << 3) + rw;
    uint32_t xB0 = (uint32_t)(rowB * 128 + ((rowB & 7) << 4));
    uint32_t xB1 = xB0 + 16 * 128;
    int cgB = mat & 1;

    float aS[4][4], aT[4][4];
#pragma unroll
    for (int f = 0; f < 4; f++)
#pragma unroll
        for (int j = 0; j < 4; j++) { aS[f][j] = 0.0f; aT[f][j] = 0.0f; }

    const uint32_t aeOff[3] = {SM_EHI, SM_EHI, SM_ELO};
    const uint32_t agOff[3] = {SM_GHI, SM_GHI, SM_GLO};
    const uint32_t bOff[3]  = {SM_CHI, SM_CLO, SM_CHI};

#pragma unroll
    for (int p = 0; p < 3; p++) {
#pragma unroll
        for (int k16 = 0; k16 < 4; k16++) {
            uint32_t ae[4], ag[4];
            uint32_t cA = (uint32_t)((2 * k16 + cgA) << 4);
            ldm4(ae, sb + aeOff[p] + (xA ^ cA));
            ldm4(ag, sb + agOff[p] + (xA ^ cA));
            uint32_t cB = (uint32_t)((2 * k16 + cgB) << 4);
#pragma unroll
            for (int g2 = 0; g2 < 2; g2++) {
                uint32_t bb[4];
                ldm4(bb, sb + bOff[p] + ((g2 ? xB1 : xB0) ^ cB));
                mma16816(aS[2 * g2],     ae, bb[0], bb[1]);
                mma16816(aS[2 * g2 + 1], ae, bb[2], bb[3]);
                mma16816(aT[2 * g2],     ag, bb[0], bb[1]);
                mma16816(aT[2 * g2 + 1], ag, bb[2], bb[3]);
            }
        }
    }

    // ---- fused epilogue: leaky + exp, reduce over m, atomic partials ----
    float l1 = 0.0f, v1 = 0.0f, l2 = 0.0f, v2 = 0.0f;
#pragma unroll
    for (int f = 0; f < 4; f++) {
        int mloc = wm * 32 + f * 8 + ((lane & 3) << 1);
#pragma unroll
        for (int j = 0; j < 2; j++) {
            if (mloc + j < mEnd) {
                float s = aS[f][j];
                s = fmaxf(s, 0.0f) + 0.2f * fminf(s, 0.0f);
                float e = __expf(s);
                l1 += e; v1 = fmaf(e, aT[f][j], v1);
                float s2 = aS[f][j + 2];
                s2 = fmaxf(s2, 0.0f) + 0.2f * fminf(s2, 0.0f);
                float e2 = __expf(s2);
                l2 += e2; v2 = fmaf(e2, aT[f][j + 2], v2);
            }
        }
    }
#pragma unroll
    for (int off = 1; off < 4; off <<= 1) {
        l1 += __shfl_xor_sync(0xffffffffu, l1, off);
        v1 += __shfl_xor_sync(0xffffffffu, v1, off);
        l2 += __shfl_xor_sync(0xffffffffu, l2, off);
        v2 += __shfl_xor_sync(0xffffffffu, v2, off);
    }
    if ((lane & 3) == 0) {
        int n1 = nt * 64 + wn * 16 + (lane >> 2);
        int idx = b * NN + n1;
        atomicAdd(&g_accL[idx], l1);
        atomicAdd(&g_accN[idx], v1);
        atomicAdd(&g_accL[idx + 8], l2);
        atomicAdd(&g_accN[idx + 8], v2);
    }
}

// ---------------- K4: finalize ----------------
__global__ void k_final(const float* __restrict__ emb, const float* __restrict__ pb,
                        float* __restrict__ out) {
    __shared__ float pbs[CC];
    int t = threadIdx.x;
    if (t < CC) pbs[t] = pb[t];
    __syncthreads();
    int i = blockIdx.x * 256 + t;
    int n = i & (NN - 1);
    const float* er = emb + (size_t)n * CC;
    float h = 0.0f;
#pragma unroll
    for (int c = 0; c < CC; c++) h = fmaf(er[c], pbs[c], h);
    float l = g_accL[i];
    out[i] = (l > 0.0f) ? (g_accN[i] / l + h) : h;
}

extern "C" void kernel_launch(void* const* d_in, const int* in_sizes, int n_in,
                              void* d_out, int out_size) {
    const float* x    = (const float*)d_in[0];
    const float* emb  = (const float*)d_in[1];
    const float* W    = (const float*)d_in[2];
    const float* pb   = (const float*)d_in[3];
    const int*   ids  = (const int*)d_in[4];
    const int*   slen = (const int*)d_in[5];
    float* out = (float*)d_out;

    k_prep<<<2304, 256>>>(emb, W);
    k_scatter<<<(BB * SS * II * CC + 255) / 256, 256>>>(x, ids, slen);
    k_compact<<<BB, 1024>>>();
    k_cvt<<<BB * MAXM / 8, 256>>>();
    k_mma<<<16 * BB * 64, 256>>>();
    k_final<<<(BB * NN) / 256, 256>>>(emb, pb, out);
}